// round 12
// baseline (speedup 1.0000x reference)
#include <cuda_runtime.h>
#include <cstdint>

// B=256 batches of N=512 x 512 binary (0/1) float32 adjacency.
constexpr int B   = 256;
constexpr int N   = 512;
constexpr int W   = N / 32;    // 16 packed words per row
constexpr int F4  = N / 4;     // 128 float4 per row
constexpr int RPC1 = 32;       // rows per pack CTA
constexpr int NPACK = B * (N / RPC1);   // 4096 pack CTAs
constexpr int RPC2 = 64;       // rows per scale CTA
constexpr int NSCALE = B * (N / RPC2);  // 2048 scale CTAs
constexpr int GRID = NPACK + NSCALE;    // 6144

// Scratch (__device__ globals: allocation-free rule).
// Transposed slot layout: word t at slot (t&3)*4+(t>>2); uint4 slot g = words
// {g, 4+g, 8+g, 12+g} — exactly what the scale role consumes.
__device__ unsigned g_bits[(size_t)B * N * W];  // 8 MB (L2-resident)
__device__ float    g_dis [(size_t)B * N];      // 512 KB
__device__ int      g_done[B];                  // pack chunks completed per batch

__global__ void reset_kernel() { g_done[threadIdx.x] = 0; }

// ---------------------------------------------------------------------------
// One kernel, two roles by bid. Pack CTAs (first 4096) never wait; scale CTAs
// (last 2048, ascending batch) gate on their batch's 16 pack flags.
// ---------------------------------------------------------------------------
__global__ void __launch_bounds__(256)
fused_roles_kernel(const float* __restrict__ adj, float* __restrict__ out) {
    const int bid  = blockIdx.x;
    const int tid  = threadIdx.x;
    const int wid  = tid >> 5;
    const int lane = tid & 31;

    if (bid < NPACK) {
        // ================= PACK role (R10 ballot version, proven) ==========
        const int batch = bid >> 4;
        const int r0    = (bid & 15) * RPC1;
        const int l16   = lane & 15;

        const float* base = adj + ((size_t)batch * N + r0 + wid * 4) * N;

        #pragma unroll
        for (int k = 0; k < 2; k++) {
            const float* p0 = base + (size_t)(2 * k)     * N;
            const float* p1 = base + (size_t)(2 * k + 1) * N;

            // Front-batch 2 rows = 32 independent coalesced LDG.32.
            float a[W], b[W];
            #pragma unroll
            for (int t = 0; t < W; t++) {
                a[t] = __ldcs(&p0[t * 32 + lane]);
                b[t] = __ldcs(&p1[t * 32 + lane]);
            }

            #pragma unroll
            for (int r = 0; r < 2; r++) {
                const float* x = (r == 0) ? a : b;
                const int ig = r0 + wid * 4 + 2 * k + r;

                unsigned myw = 0;
                #pragma unroll
                for (int t = 0; t < W; t++) {
                    unsigned bt = __ballot_sync(0xffffffffu, x[t] != 0.0f);
                    if (l16 == t) myw = bt;
                }

                int cnt = __popc(myw);
                cnt += __shfl_xor_sync(0xffffffffu, cnt, 1);
                cnt += __shfl_xor_sync(0xffffffffu, cnt, 2);
                cnt += __shfl_xor_sync(0xffffffffu, cnt, 4);
                cnt += __shfl_xor_sync(0xffffffffu, cnt, 8);

                const int dw = ig >> 5, db = ig & 31;
                const unsigned diagw = __shfl_sync(0xffffffffu, myw, dw);
                const int diag = (diagw >> db) & 1;
                const int mask = (cnt != 0) ? 1 : 0;   // atom_mask
                const int deg  = cnt - diag + mask;    // degree_hat
                if (diag != mask && l16 == dw) myw ^= (1u << db);

                if (lane < 16)
                    g_bits[((size_t)batch * N + ig) * W + (lane & 3) * 4 + (lane >> 2)] = myw;
                if (lane == 0)
                    g_dis[(size_t)batch * N + ig] = (deg > 0) ? rsqrtf((float)deg) : 0.0f;
            }
        }

        // Release: stores -> fence -> barrier -> flag bump.
        __threadfence();
        __syncthreads();
        if (tid == 0) atomicAdd(&g_done[batch], 1);

    } else {
        // ================= SCALE role (R8 body, 4-row front-batch) =========
        const int sb    = bid - NPACK;
        const int batch = sb >> 3;            // ascending: matches pack order
        const int r0    = (sb & 7) * RPC2;
        const int sub   = lane & 7;
        const int grp   = lane >> 3;
        const int lr    = r0 + wid * 8;       // first of 8 rows for this warp

        // Acquire: wait for this batch's 16 pack chunks.
        if (tid == 0) {
            volatile int* vf = &g_done[batch];
            while (*vf != 16) __nanosleep(64);
        }
        __syncthreads();
        __threadfence();

        // Row-invariant column scales (L2-hot).
        const float4* d4 = reinterpret_cast<const float4*>(g_dis + (size_t)batch * N);
        float4 dreg[4];
        #pragma unroll
        for (int c = 0; c < 4; c++) dreg[c] = __ldcg(&d4[c * 32 + lane]);

        const uint4* b4 = reinterpret_cast<const uint4*>(g_bits)
                        + ((size_t)batch * N + lr) * 4;
        float4* o4 = reinterpret_cast<float4*>(out) + ((size_t)batch * N + lr) * F4;

        #pragma unroll
        for (int h = 0; h < 2; h++) {
            // Front-batch 4 rows' words + scales (keeps unified kernel <=~58 regs).
            uint4 wb[4];
            float di[4];
            #pragma unroll
            for (int r = 0; r < 4; r++) {
                wb[r] = __ldcg(&b4[(size_t)(4 * h + r) * 4 + grp]);
                di[r] = __ldcg(&g_dis[(size_t)batch * N + lr + 4 * h + r]);
            }
            #pragma unroll
            for (int r = 0; r < 4; r++) {
                float4* q = o4 + (size_t)(4 * h + r) * F4;
                const unsigned wc[4] = {wb[r].x, wb[r].y, wb[r].z, wb[r].w};
                #pragma unroll
                for (int c = 0; c < 4; c++) {
                    const unsigned nib = (wc[c] >> (sub * 4)) & 0xFu;
                    const float4 d = dreg[c];
                    float4 o;
                    o.x = (nib & 1u) ? di[r] * d.x : 0.0f;
                    o.y = (nib & 2u) ? di[r] * d.y : 0.0f;
                    o.z = (nib & 4u) ? di[r] * d.z : 0.0f;
                    o.w = (nib & 8u) ? di[r] * d.w : 0.0f;
                    __stcs(&q[c * 32 + lane], o);  // coalesced STG.128 stream
                }
            }
        }
    }
}

extern "C" void kernel_launch(void* const* d_in, const int* in_sizes, int n_in,
                              void* d_out, int out_size) {
    const float* adj = (const float*)d_in[0];
    float* out = (float*)d_out;
    (void)in_sizes; (void)n_in; (void)out_size;

    reset_kernel<<<1, B>>>();
    fused_roles_kernel<<<GRID, 256>>>(adj, out);
}

// round 13
// speedup vs baseline: 1.4284x; 1.4284x over previous
#include <cuda_runtime.h>
#include <cstdint>

// B=256 batches of N=512 x 512 binary (0/1) float32 adjacency.
constexpr int B   = 256;
constexpr int N   = 512;
constexpr int W   = N / 32;    // 16 packed words per row
constexpr int F4  = N / 4;     // 128 float4 per row
constexpr int RPC1 = 32;       // rows per CTA, pack kernel
constexpr int GRID1 = B * (N / RPC1);  // 4096
constexpr int RPC2 = 64;       // rows per CTA, scale kernel
constexpr int GRID2 = B * (N / RPC2);  // 2048

// Scratch (__device__ globals: allocation-free rule).
// Transposed slot layout: word t lives at slot (t&3)*4 + (t>>2), so the uint4
// at slot-index g = words {g, 4+g, 8+g, 12+g} (exactly what K2 consumes).
__device__ unsigned g_bits[(size_t)B * N * W];  // 8 MB (L2-resident)
__device__ float    g_dis [(size_t)B * N];      // 512 KB

// ---------------------------------------------------------------------------
// K1: one warp per row, ballot packing (proven in R10). 8 warps x 4 rows =
// 32 rows/CTA; 2 rows front-batched (32 independent coalesced LDG.32).
// Ends with fence + explicit PDL trigger so K2 ramps during K1's drain.
// ---------------------------------------------------------------------------
__global__ void __launch_bounds__(256)
pack_kernel(const float* __restrict__ adj) {
    const int bid   = blockIdx.x;
    const int batch = bid >> 4;
    const int r0    = (bid & 15) * RPC1;

    const int tid  = threadIdx.x;
    const int wid  = tid >> 5;
    const int lane = tid & 31;
    const int l16  = lane & 15;

    const float* base = adj + ((size_t)batch * N + r0 + wid * 4) * N;

    #pragma unroll
    for (int k = 0; k < 2; k++) {
        const float* p0 = base + (size_t)(2 * k)     * N;
        const float* p1 = base + (size_t)(2 * k + 1) * N;

        // Front-batch 2 rows = 32 independent coalesced LDG.32 (128B/wavefront).
        float a[W], b[W];
        #pragma unroll
        for (int t = 0; t < W; t++) {
            a[t] = __ldcs(&p0[t * 32 + lane]);
            b[t] = __ldcs(&p1[t * 32 + lane]);
        }

        #pragma unroll
        for (int r = 0; r < 2; r++) {
            const float* x = (r == 0) ? a : b;
            const int ig = r0 + wid * 4 + 2 * k + r;   // row index within batch

            // 16 independent ballots; lane l keeps word l (l<16).
            unsigned myw = 0;
            #pragma unroll
            for (int t = 0; t < W; t++) {
                unsigned bt = __ballot_sync(0xffffffffu, x[t] != 0.0f);
                if (l16 == t) myw = bt;
            }

            // Degree: popc of own word, xor-reduce over the 16-lane group.
            int cnt = __popc(myw);
            cnt += __shfl_xor_sync(0xffffffffu, cnt, 1);
            cnt += __shfl_xor_sync(0xffffffffu, cnt, 2);
            cnt += __shfl_xor_sync(0xffffffffu, cnt, 4);
            cnt += __shfl_xor_sync(0xffffffffu, cnt, 8);

            const int dw = ig >> 5, db = ig & 31;
            const unsigned diagw = __shfl_sync(0xffffffffu, myw, dw);
            const int diag = (diagw >> db) & 1;
            const int mask = (cnt != 0) ? 1 : 0;       // atom_mask
            const int deg  = cnt - diag + mask;        // degree_hat
            if (diag != mask && l16 == dw) myw ^= (1u << db);

            // Transposed-slot store: word l -> slot (l&3)*4 + (l>>2).
            if (lane < 16)
                g_bits[((size_t)batch * N + ig) * W + (lane & 3) * 4 + (lane >> 2)] = myw;
            if (lane == 0)
                g_dis[(size_t)batch * N + ig] = (deg > 0) ? rsqrtf((float)deg) : 0.0f;
        }
    }

    // Early PDL trigger: stores above are made visible, then signal that this
    // CTA will issue no more dependent-relevant work. K2's grid launches once
    // ALL K1 CTAs have triggered (before their epilogue/drain completes).
    __threadfence();
    cudaTriggerProgrammaticLaunchCompletion();
}

// ---------------------------------------------------------------------------
// K2: out[i][j] = dis[i]*dis[j]*bit(i,j). Proven at the write cap — unchanged
// from R10 (ascending batch order). 8 warps x 8 rows = 64 rows/CTA. PDL entry.
// ---------------------------------------------------------------------------
__global__ void __launch_bounds__(256)
scale_kernel(float* __restrict__ out) {
    const int bid   = blockIdx.x;
    const int batch = bid >> 3;
    const int r0    = (bid & 7) * RPC2;

    const int tid  = threadIdx.x;
    const int wid  = tid >> 5;
    const int lane = tid & 31;
    const int sub  = lane & 7;
    const int grp  = lane >> 3;

    const int lr = r0 + wid * 8;   // first of 8 rows for this warp (within batch)

    // PDL: wait until all pack_kernel CTAs have fenced + triggered.
    cudaGridDependencySynchronize();

    // Row-invariant column scales: dreg[c] = dis[c*128 + lane*4 .. +3].
    const float4* d4 = reinterpret_cast<const float4*>(g_dis + (size_t)batch * N);
    float4 dreg[4];
    #pragma unroll
    for (int c = 0; c < 4; c++) dreg[c] = __ldg(&d4[c * 32 + lane]);

    // Front-batch the 8 rows' packed words (one aligned uint4 per lane-group,
    // L2-resident) and the 8 row scales.
    const uint4* b4 = reinterpret_cast<const uint4*>(g_bits)
                    + ((size_t)batch * N + lr) * 4;
    uint4 wb[8];
    #pragma unroll
    for (int r = 0; r < 8; r++) wb[r] = __ldcg(&b4[(size_t)r * 4 + grp]);

    float di[8];
    #pragma unroll
    for (int r = 0; r < 8; r++) di[r] = __ldg(&g_dis[(size_t)batch * N + lr + r]);

    float4* o4 = reinterpret_cast<float4*>(out) + ((size_t)batch * N + lr) * F4;

    #pragma unroll
    for (int r = 0; r < 8; r++) {
        float4* q = o4 + (size_t)r * F4;
        const unsigned wc[4] = {wb[r].x, wb[r].y, wb[r].z, wb[r].w};  // word c*4+grp
        #pragma unroll
        for (int c = 0; c < 4; c++) {
            const unsigned nib = (wc[c] >> (sub * 4)) & 0xFu;
            const float4 d = dreg[c];
            float4 o;
            o.x = (nib & 1u) ? di[r] * d.x : 0.0f;
            o.y = (nib & 2u) ? di[r] * d.y : 0.0f;
            o.z = (nib & 4u) ? di[r] * d.z : 0.0f;
            o.w = (nib & 8u) ? di[r] * d.w : 0.0f;
            __stcs(&q[c * 32 + lane], o);  // coalesced STG.128 stream
        }
    }
}

extern "C" void kernel_launch(void* const* d_in, const int* in_sizes, int n_in,
                              void* d_out, int out_size) {
    const float* adj = (const float*)d_in[0];
    float* out = (float*)d_out;
    (void)in_sizes; (void)n_in; (void)out_size;

    pack_kernel<<<GRID1, 256>>>(adj);

    // PDL launch: K2 may begin once all K1 CTAs have triggered (early, after
    // their stores + fence) rather than after full grid drain.
    cudaLaunchConfig_t cfg = {};
    cfg.gridDim  = dim3(GRID2);
    cfg.blockDim = dim3(256);
    cudaLaunchAttribute attr[1];
    attr[0].id = cudaLaunchAttributeProgrammaticStreamSerialization;
    attr[0].val.programmaticStreamSerializationAllowed = 1;
    cfg.attrs = attr;
    cfg.numAttrs = 1;
    cudaLaunchKernelEx(&cfg, scale_kernel, out);
}